// round 1
// baseline (speedup 1.0000x reference)
#include <cuda_runtime.h>
#include <math.h>

// Problem dims
#define BB 4
#define SS 1024
#define DD 1024
#define HH 16
#define HD 64
#define FF 4096
#define VV 32000
#define LL 2
#define TT (BB*SS)   // 4096 tokens

// ---------------- scratch (device globals: no allocation allowed) ----------
__device__ float g_h[TT*DD];
__device__ float g_q[TT*DD];
__device__ float g_k[TT*DD];
__device__ float g_v[TT*DD];
__device__ float g_attn[TT*DD];
__device__ float g_tmp[TT*DD];
__device__ float g_ff[(size_t)TT*FF];
__device__ float g_wq[DD*DD];
__device__ float g_wk[DD*DD];
__device__ float g_wv[DD*DD];
__device__ int   g_flag[1];

// ---------------- token dtype sniffer (int64 vs int32) ---------------------
// If x is int64 (values < 2^31), the odd int32 words of the first 4096 words
// are all zero. If int32, they are real tokens (all-zero prob ~ 0).
__global__ void detect_kernel(const int* __restrict__ x32, int* __restrict__ flag) {
    __shared__ int sh;
    if (threadIdx.x == 0) sh = 0;
    __syncthreads();
    int acc = 0;
    for (int i = threadIdx.x; i < TT/2; i += blockDim.x) acc |= x32[2*i + 1];
    #pragma unroll
    for (int o = 16; o; o >>= 1) acc |= __shfl_xor_sync(0xffffffffu, acc, o);
    if ((threadIdx.x & 31) == 0) atomicOr(&sh, acc);
    __syncthreads();
    if (threadIdx.x == 0) *flag = (sh != 0) ? 1 : 0;  // 1 => int32, 0 => int64
}

// ---------------- embedding -------------------------------------------------
__global__ void embed_kernel(const void* __restrict__ x,
                             const float* __restrict__ tok,
                             const float* __restrict__ pos,
                             float* __restrict__ h,
                             const int* __restrict__ flag) {
    int t = blockIdx.x;
    int idx;
    if (*flag) idx = ((const int*)x)[t];
    else       idx = (int)(((const long long*)x)[t]);
    int s = t & (SS - 1);
    const float4* tp = (const float4*)(tok + (size_t)idx * DD);
    const float4* pp = (const float4*)(pos + (size_t)s * DD);
    float4* hp = (float4*)(h + (size_t)t * DD);
    int i = threadIdx.x;  // 256 threads, DD/4 = 256
    float4 a = tp[i], b = pp[i];
    hp[i] = make_float4(a.x + b.x, a.y + b.y, a.z + b.z, a.w + b.w);
}

// ---------------- repack per-head QKV weights [H][D][HD] -> [D][H*HD] -------
__global__ void repack_kernel(const float* __restrict__ src, float* __restrict__ dst) {
    int i = blockIdx.x * 256 + threadIdx.x;   // over D*H*HD = 1M
    int d  = i >> 10;
    int he = i & 1023;
    int hh = he >> 6;
    int e  = he & 63;
    dst[i] = src[((size_t)(hh << 10) + d) * HD + e];
}

// ---------------- SGEMM: C = A[M,K] * B[K,N] + bias[N], optional exact GELU --
#define Bb 128
#define Bn 128
#define Bk 8
#define Tm 8
#define Tn 8

template<bool GELU>
__global__ __launch_bounds__(256, 2)
void sgemm_kernel(const float* __restrict__ A, const float* __restrict__ Bm,
                  const float* __restrict__ bias, float* __restrict__ C,
                  int M, int N, int K) {
    __shared__ float As[Bk][Bb];
    __shared__ float Bs[Bk][Bn];

    int tid = threadIdx.x;
    int row0 = blockIdx.y * Bb;
    int col0 = blockIdx.x * Bn;

    int arow = tid >> 1;            // 0..127
    int acol = (tid & 1) * 4;       // 0 or 4
    int brow = tid >> 5;            // 0..7
    int bcol = (tid & 31) * 4;      // 0..124

    int tr = (tid >> 4) * Tm;       // 0..120
    int tc = (tid & 15) * Tn;       // 0..120

    const float* Aptr = A + (size_t)(row0 + arow) * K + acol;
    const float* Bptr = Bm + (size_t)brow * N + col0 + bcol;

    float acc[Tm][Tn];
    #pragma unroll
    for (int i = 0; i < Tm; i++)
        #pragma unroll
        for (int j = 0; j < Tn; j++) acc[i][j] = 0.f;

    int nk = K / Bk;
    float4 a4 = *(const float4*)(Aptr);
    float4 b4 = *(const float4*)(Bptr);

    for (int t = 0; t < nk; t++) {
        As[acol + 0][arow] = a4.x;
        As[acol + 1][arow] = a4.y;
        As[acol + 2][arow] = a4.z;
        As[acol + 3][arow] = a4.w;
        *(float4*)&Bs[brow][bcol] = b4;
        __syncthreads();

        if (t + 1 < nk) {
            a4 = *(const float4*)(Aptr + (t + 1) * Bk);
            b4 = *(const float4*)(Bptr + (size_t)(t + 1) * Bk * N);
        }

        #pragma unroll
        for (int k = 0; k < Bk; k++) {
            float4 ra0 = *(const float4*)&As[k][tr];
            float4 ra1 = *(const float4*)&As[k][tr + 4];
            float4 rb0 = *(const float4*)&Bs[k][tc];
            float4 rb1 = *(const float4*)&Bs[k][tc + 4];
            float ra[Tm] = {ra0.x, ra0.y, ra0.z, ra0.w, ra1.x, ra1.y, ra1.z, ra1.w};
            float rb[Tn] = {rb0.x, rb0.y, rb0.z, rb0.w, rb1.x, rb1.y, rb1.z, rb1.w};
            #pragma unroll
            for (int i = 0; i < Tm; i++)
                #pragma unroll
                for (int j = 0; j < Tn; j++)
                    acc[i][j] = fmaf(ra[i], rb[j], acc[i][j]);
        }
        __syncthreads();
    }

    // epilogue
    #pragma unroll
    for (int i = 0; i < Tm; i++) {
        size_t rbase = (size_t)(row0 + tr + i) * N + col0 + tc;
        #pragma unroll
        for (int j4 = 0; j4 < Tn; j4 += 4) {
            float4 v;
            float* vp = &v.x;
            #pragma unroll
            for (int c = 0; c < 4; c++) {
                float val = acc[i][j4 + c] + bias[col0 + tc + j4 + c];
                if (GELU) val = 0.5f * val * (1.f + erff(val * 0.70710678118654752f));
                vp[c] = val;
            }
            *(float4*)&C[rbase + j4] = v;
        }
    }
}

// ---------------- flash attention: per (b, h, q-tile of 64) -----------------
// Q,K,V,O: [T][H*HD] row-major; this CTA handles rows q0..q0+63 of head h.
#define PAD 65
__global__ __launch_bounds__(256)
void attn_kernel(const float* __restrict__ Q, const float* __restrict__ K,
                 const float* __restrict__ V, float* __restrict__ O) {
    extern __shared__ float sm[];
    float* Qs = sm;                 // [64][PAD]  stored [e][r]
    float* Ks = Qs + 64 * PAD;      // [64][PAD]  stored [e][kk]
    float* Vs = Ks + 64 * PAD;      // [64][PAD]  stored [kk][e]
    float* Ps = Vs + 64 * PAD;      // [64][PAD]  stored [r][kk]
    float* s_alpha = Ps + 64 * PAD; // [64]
    float* s_l     = s_alpha + 64;  // [64]

    int tid = threadIdx.x;
    int tx = tid & 15, ty = tid >> 4;
    int qt = blockIdx.x, h = blockIdx.y, b = blockIdx.z;
    int q0 = qt * 64;
    int base = b * SS * DD + h * HD;   // offset of (b, s=0, h, e=0)

    for (int i = tid; i < 4096; i += 256) {
        int r = i >> 6, e = i & 63;
        Qs[e * PAD + r] = Q[base + (q0 + r) * DD + e];
    }
    float o[4][4];
    #pragma unroll
    for (int i = 0; i < 4; i++)
        #pragma unroll
        for (int j = 0; j < 4; j++) o[i][j] = 0.f;
    float m_t = -1e30f, l_t = 0.f;
    __syncthreads();

    for (int kt = 0; kt <= qt; kt++) {
        int k0 = kt * 64;
        for (int i = tid; i < 4096; i += 256) {
            int r = i >> 6, e = i & 63;
            float kv = K[base + (k0 + r) * DD + e];
            float vv = V[base + (k0 + r) * DD + e];
            Ks[e * PAD + r] = kv;
            Vs[r * PAD + e] = vv;
        }
        __syncthreads();

        // S = Q K^T (4x4 per thread over 64-dim)
        float s[4][4];
        #pragma unroll
        for (int i = 0; i < 4; i++)
            #pragma unroll
            for (int j = 0; j < 4; j++) s[i][j] = 0.f;
        for (int d = 0; d < 64; d++) {
            float qa[4], kb[4];
            #pragma unroll
            for (int i = 0; i < 4; i++) qa[i] = Qs[d * PAD + 4 * ty + i];
            #pragma unroll
            for (int j = 0; j < 4; j++) kb[j] = Ks[d * PAD + 4 * tx + j];
            #pragma unroll
            for (int i = 0; i < 4; i++)
                #pragma unroll
                for (int j = 0; j < 4; j++)
                    s[i][j] = fmaf(qa[i], kb[j], s[i][j]);
        }
        // scale + causal mask, write P-scores to shared
        #pragma unroll
        for (int i = 0; i < 4; i++)
            #pragma unroll
            for (int j = 0; j < 4; j++) {
                float sv = s[i][j] * 0.125f;  // 1/sqrt(64)
                if (k0 + 4 * tx + j > q0 + 4 * ty + i) sv = -1e30f;
                Ps[(4 * ty + i) * PAD + 4 * tx + j] = sv;
            }
        __syncthreads();

        // online softmax per row (threads 0..63 own one row each)
        if (tid < 64) {
            float mx = m_t;
            #pragma unroll 8
            for (int kk = 0; kk < 64; kk++) mx = fmaxf(mx, Ps[tid * PAD + kk]);
            float alpha = __expf(m_t - mx);
            float ssum = 0.f;
            #pragma unroll 8
            for (int kk = 0; kk < 64; kk++) {
                float p = __expf(Ps[tid * PAD + kk] - mx);
                Ps[tid * PAD + kk] = p;
                ssum += p;
            }
            l_t = l_t * alpha + ssum;
            m_t = mx;
            s_alpha[tid] = alpha;
            s_l[tid] = l_t;
        }
        __syncthreads();

        // O = alpha*O + P V
        float al[4];
        #pragma unroll
        for (int i = 0; i < 4; i++) al[i] = s_alpha[4 * ty + i];
        #pragma unroll
        for (int i = 0; i < 4; i++)
            #pragma unroll
            for (int j = 0; j < 4; j++) o[i][j] *= al[i];
        for (int kk = 0; kk < 64; kk++) {
            float p[4], vv[4];
            #pragma unroll
            for (int i = 0; i < 4; i++) p[i] = Ps[(4 * ty + i) * PAD + kk];
            #pragma unroll
            for (int j = 0; j < 4; j++) vv[j] = Vs[kk * PAD + 4 * tx + j];
            #pragma unroll
            for (int i = 0; i < 4; i++)
                #pragma unroll
                for (int j = 0; j < 4; j++)
                    o[i][j] = fmaf(p[i], vv[j], o[i][j]);
        }
        __syncthreads();
    }

    float linv[4];
    #pragma unroll
    for (int i = 0; i < 4; i++) linv[i] = 1.f / s_l[4 * ty + i];
    #pragma unroll
    for (int i = 0; i < 4; i++)
        #pragma unroll
        for (int j = 0; j < 4; j++)
            O[base + (q0 + 4 * ty + i) * DD + 4 * tx + j] = o[i][j] * linv[i];
}

// ---------------- fused residual + LayerNorm --------------------------------
__inline__ __device__ float warp_sum(float v) {
    #pragma unroll
    for (int o = 16; o; o >>= 1) v += __shfl_xor_sync(0xffffffffu, v, o);
    return v;
}

__global__ __launch_bounds__(256)
void resid_ln_kernel(const float* __restrict__ a, const float* __restrict__ r,
                     const float* __restrict__ w, const float* __restrict__ bb,
                     float* __restrict__ out) {
    int row = blockIdx.x, tid = threadIdx.x;
    const float4* pa = (const float4*)(a + (size_t)row * DD);
    const float4* pr = (const float4*)(r + (size_t)row * DD);
    float4 av = pa[tid], rv = pr[tid];
    float x0 = av.x + rv.x, x1 = av.y + rv.y, x2 = av.z + rv.z, x3 = av.w + rv.w;
    float s  = x0 + x1 + x2 + x3;
    float s2 = x0 * x0 + x1 * x1 + x2 * x2 + x3 * x3;
    s = warp_sum(s);
    s2 = warp_sum(s2);
    __shared__ float sh[2][8];
    int wid = tid >> 5;
    if ((tid & 31) == 0) { sh[0][wid] = s; sh[1][wid] = s2; }
    __syncthreads();
    if (tid == 0) {
        float S = 0.f, S2 = 0.f;
        #pragma unroll
        for (int i = 0; i < 8; i++) { S += sh[0][i]; S2 += sh[1][i]; }
        sh[0][0] = S; sh[1][0] = S2;
    }
    __syncthreads();
    float mean = sh[0][0] * (1.f / DD);
    float var  = sh[1][0] * (1.f / DD) - mean * mean;
    float rstd = rsqrtf(var + 1e-5f);
    const float4* pw = (const float4*)w;
    const float4* pb = (const float4*)bb;
    float4 wv = pw[tid], bv = pb[tid];
    float4 ov;
    ov.x = (x0 - mean) * rstd * wv.x + bv.x;
    ov.y = (x1 - mean) * rstd * wv.y + bv.y;
    ov.z = (x2 - mean) * rstd * wv.z + bv.z;
    ov.w = (x3 - mean) * rstd * wv.w + bv.w;
    ((float4*)(out + (size_t)row * DD))[tid] = ov;
}

// ---------------- simple copy ------------------------------------------------
__global__ void copy_kernel(const float* __restrict__ src, float* __restrict__ dst) {
    int i = blockIdx.x * 256 + threadIdx.x;
    ((float4*)dst)[i] = ((const float4*)src)[i];
}

// ---------------- host ------------------------------------------------------
extern "C" void kernel_launch(void* const* d_in, const int* in_sizes, int n_in,
                              void* d_out, int out_size) {
    const void*  x    = d_in[0];
    const float* tok  = (const float*)d_in[1];
    const float* pos  = (const float*)d_in[2];
    const float* Wq   = (const float*)d_in[3];
    const float* bq   = (const float*)d_in[4];
    const float* Wk   = (const float*)d_in[5];
    const float* bk   = (const float*)d_in[6];
    const float* Wv   = (const float*)d_in[7];
    const float* bv   = (const float*)d_in[8];
    const float* Wo   = (const float*)d_in[9];
    const float* bo   = (const float*)d_in[10];
    const float* ln1w = (const float*)d_in[11];
    const float* ln1b = (const float*)d_in[12];
    const float* ln2w = (const float*)d_in[13];
    const float* ln2b = (const float*)d_in[14];
    const float* W1   = (const float*)d_in[15];
    const float* b1   = (const float*)d_in[16];
    const float* W2   = (const float*)d_in[17];
    const float* b2   = (const float*)d_in[18];
    const float* Wout = (const float*)d_in[19];
    const float* bout = (const float*)d_in[20];
    float* out = (float*)d_out;

    float *h, *q, *k, *v, *attn, *tmp, *ff, *wq, *wk, *wv;
    int* flag;
    cudaGetSymbolAddress((void**)&h,    g_h);
    cudaGetSymbolAddress((void**)&q,    g_q);
    cudaGetSymbolAddress((void**)&k,    g_k);
    cudaGetSymbolAddress((void**)&v,    g_v);
    cudaGetSymbolAddress((void**)&attn, g_attn);
    cudaGetSymbolAddress((void**)&tmp,  g_tmp);
    cudaGetSymbolAddress((void**)&ff,   g_ff);
    cudaGetSymbolAddress((void**)&wq,   g_wq);
    cudaGetSymbolAddress((void**)&wk,   g_wk);
    cudaGetSymbolAddress((void**)&wv,   g_wv);
    cudaGetSymbolAddress((void**)&flag, g_flag);

    const int smem_attn = 4 * 64 * PAD * 4 + 2 * 64 * 4;  // 67072 B
    cudaFuncSetAttribute(attn_kernel, cudaFuncAttributeMaxDynamicSharedMemorySize, smem_attn);

    detect_kernel<<<1, 256>>>((const int*)x, flag);
    embed_kernel<<<TT, 256>>>(x, tok, pos, h, flag);

    for (int l = 0; l < LL; l++) {
        size_t woff = (size_t)l * HH * DD * HD;
        repack_kernel<<<DD * DD / 256, 256>>>(Wq + woff, wq);
        repack_kernel<<<DD * DD / 256, 256>>>(Wk + woff, wk);
        repack_kernel<<<DD * DD / 256, 256>>>(Wv + woff, wv);

        dim3 g1(DD / Bn, TT / BB * 0 + TT / 128);
        g1 = dim3(DD / 128, TT / 128);
        sgemm_kernel<false><<<g1, 256>>>(h, wq, bq + l * DD, q, TT, DD, DD);
        sgemm_kernel<false><<<g1, 256>>>(h, wk, bk + l * DD, k, TT, DD, DD);
        sgemm_kernel<false><<<g1, 256>>>(h, wv, bv + l * DD, v, TT, DD, DD);

        dim3 ga(SS / 64, HH, BB);
        attn_kernel<<<ga, 256, smem_attn>>>(q, k, v, attn);

        sgemm_kernel<false><<<g1, 256>>>(attn, Wo + (size_t)l * DD * DD, bo + l * DD,
                                         tmp, TT, DD, DD);
        resid_ln_kernel<<<TT, 256>>>(h, tmp, ln1w + l * DD, ln1b + l * DD, h);

        dim3 g2(FF / 128, TT / 128);
        sgemm_kernel<true><<<g2, 256>>>(h, W1 + (size_t)l * DD * FF, b1 + l * FF,
                                        ff, TT, FF, DD);
        dim3 g3(DD / 128, TT / 128);
        sgemm_kernel<false><<<g3, 256>>>(ff, W2 + (size_t)l * FF * DD, b2 + l * DD,
                                         tmp, TT, DD, FF);
        resid_ln_kernel<<<TT, 256>>>(h, tmp, ln2w + l * DD, ln2b + l * DD, h);
    }

    dim3 g4(VV / 128, TT / 128);
    sgemm_kernel<false><<<g4, 256>>>(h, Wout, bout, out, TT, VV, DD);
    copy_kernel<<<TT * DD / 4 / 256, 256>>>(h, out + (size_t)TT * VV);
}

// round 3
// speedup vs baseline: 3.8292x; 3.8292x over previous
#include <cuda_runtime.h>
#include <cuda_fp16.h>
#include <cstdint>
#include <math.h>

typedef unsigned int u32;

#define BB 4
#define SS 1024
#define DD 1024
#define HH 16
#define HD 64
#define FF 4096
#define VV 32000
#define LL 2
#define TT (BB*SS)

// scratch (device globals: allocation is forbidden)
__device__ float g_h[TT*DD];
__device__ float g_q[TT*DD];
__device__ float g_k[TT*DD];
__device__ float g_v[TT*DD];
__device__ float g_attn[TT*DD];
__device__ float g_tmp[TT*DD];
__device__ __half g_a16[TT*DD];
__device__ __half g_ff16[(size_t)TT*FF];
__device__ __half g_wq16[DD*DD];
__device__ __half g_wk16[DD*DD];
__device__ __half g_wv16[DD*DD];
__device__ __half g_wo16[DD*DD];
__device__ __half g_w1h[(size_t)DD*FF];
__device__ __half g_w2h[(size_t)FF*DD];
__device__ __half g_wouth[(size_t)DD*VV];
__device__ int   g_flag[1];

// token dtype sniffer: int64 tokens (<2^31) have all-zero odd words
__global__ void detect_kernel(const int* __restrict__ x32, int* __restrict__ flag) {
    __shared__ int sh;
    if (threadIdx.x == 0) sh = 0;
    __syncthreads();
    int acc = 0;
    for (int i = threadIdx.x; i < TT/2; i += blockDim.x) acc |= x32[2*i + 1];
    #pragma unroll
    for (int o = 16; o; o >>= 1) acc |= __shfl_xor_sync(0xffffffffu, acc, o);
    if ((threadIdx.x & 31) == 0) atomicOr(&sh, acc);
    __syncthreads();
    if (threadIdx.x == 0) *flag = (sh != 0) ? 1 : 0;
}

__global__ void embed_kernel(const void* __restrict__ x,
                             const float* __restrict__ tok,
                             const float* __restrict__ pos,
                             float* __restrict__ h,
                             const int* __restrict__ flag) {
    int t = blockIdx.x;
    int idx;
    if (*flag) idx = ((const int*)x)[t];
    else       idx = (int)(((const long long*)x)[t]);
    int s = t & (SS - 1);
    const float4* tp = (const float4*)(tok + (size_t)idx * DD);
    const float4* pp = (const float4*)(pos + (size_t)s * DD);
    float4* hp = (float4*)(h + (size_t)t * DD);
    int i = threadIdx.x;
    float4 a = tp[i], b = pp[i];
    hp[i] = make_float4(a.x + b.x, a.y + b.y, a.z + b.z, a.w + b.w);
}

// repack [H][D][HD] -> [D][H*HD] as fp16
__global__ void repack_kernel(const float* __restrict__ src, __half* __restrict__ dst) {
    int i = blockIdx.x * 256 + threadIdx.x;
    int d  = i >> 10;
    int he = i & 1023;
    int hh = he >> 6;
    int e  = he & 63;
    dst[i] = __float2half(src[((size_t)(hh << 10) + d) * HD + e]);
}

__global__ void f2h_kernel(const float* __restrict__ src, __half* __restrict__ dst,
                           int n4) {
    int i = blockIdx.x * 256 + threadIdx.x;
    if (i >= n4) return;
    float4 v = ((const float4*)src)[i];
    ((__half2*)dst)[2*i]     = __floats2half2_rn(v.x, v.y);
    ((__half2*)dst)[2*i + 1] = __floats2half2_rn(v.z, v.w);
}

// ---------------- fp16 tensor-core GEMM ------------------------------------
#define HBM 128
#define HBN 128
#define HBK 32
#define APAD 8
#define BPAD 8

__device__ __forceinline__ void ldm_x4(u32* r, u32 addr) {
    asm volatile("ldmatrix.sync.aligned.m8n8.x4.shared.b16 {%0,%1,%2,%3}, [%4];"
        : "=r"(r[0]), "=r"(r[1]), "=r"(r[2]), "=r"(r[3]) : "r"(addr));
}
__device__ __forceinline__ void ldm_x4_t(u32* r, u32 addr) {
    asm volatile("ldmatrix.sync.aligned.m8n8.x4.trans.shared.b16 {%0,%1,%2,%3}, [%4];"
        : "=r"(r[0]), "=r"(r[1]), "=r"(r[2]), "=r"(r[3]) : "r"(addr));
}
__device__ __forceinline__ void mma16816(float* d, const u32* a, u32 b0, u32 b1) {
    asm volatile("mma.sync.aligned.m16n8k16.row.col.f32.f16.f16.f32 "
        "{%0,%1,%2,%3}, {%4,%5,%6,%7}, {%8,%9}, {%0,%1,%2,%3};"
        : "+f"(d[0]), "+f"(d[1]), "+f"(d[2]), "+f"(d[3])
        : "r"(a[0]), "r"(a[1]), "r"(a[2]), "r"(a[3]), "r"(b0), "r"(b1));
}
__device__ __forceinline__ void cpa16(u32 s, const void* g) {
    asm volatile("cp.async.cg.shared.global [%0], [%1], 16;" :: "r"(s), "l"(g));
}
__device__ __forceinline__ u32 s2u(const void* p) {
    return (u32)__cvta_generic_to_shared(p);
}

template<bool GELU, bool OUTH>
__global__ __launch_bounds__(256)
void hgemm_kernel(const __half* __restrict__ A, const __half* __restrict__ B,
                  const float* __restrict__ bias, void* __restrict__ Cout,
                  int M, int N, int K) {
    __shared__ __half As[2][HBM][HBK + APAD];
    __shared__ __half Bs[2][HBK][HBN + BPAD];

    int tid = threadIdx.x;
    int lane = tid & 31, warp = tid >> 5;
    int row0 = blockIdx.y * HBM;
    int col0 = blockIdx.x * HBN;
    int wr = (warp & 3) * 32;
    int wc = (warp >> 2) * 64;

    int arow = tid >> 1, acol = (tid & 1) * 16;
    int brow = tid >> 3, bcol = (tid & 7) * 16;
    const __half* Ag = A + (size_t)(row0 + arow) * K + acol;
    const __half* Bg = B + (size_t)brow * N + col0 + bcol;

    u32 sA0 = s2u(&As[0][arow][acol]);
    u32 sA1 = s2u(&As[1][arow][acol]);
    u32 sB0 = s2u(&Bs[0][brow][bcol]);
    u32 sB1 = s2u(&Bs[1][brow][bcol]);

    float acc[2][8][4];
    #pragma unroll
    for (int i = 0; i < 2; i++)
        #pragma unroll
        for (int j = 0; j < 8; j++)
            #pragma unroll
            for (int c = 0; c < 4; c++) acc[i][j][c] = 0.f;

    int nk = K / HBK;
    cpa16(sA0, Ag);       cpa16(sA0 + 16, Ag + 8);
    cpa16(sB0, Bg);       cpa16(sB0 + 16, Bg + 8);
    asm volatile("cp.async.commit_group;" ::);

    for (int t = 0; t < nk; t++) {
        asm volatile("cp.async.wait_group 0;" ::);
        __syncthreads();
        if (t + 1 < nk) {
            u32 sa = ((t + 1) & 1) ? sA1 : sA0;
            u32 sb = ((t + 1) & 1) ? sB1 : sB0;
            const __half* ag = Ag + (size_t)(t + 1) * HBK;
            const __half* bg = Bg + (size_t)(t + 1) * HBK * N;
            cpa16(sa, ag);       cpa16(sa + 16, ag + 8);
            cpa16(sb, bg);       cpa16(sb + 16, bg + 8);
            asm volatile("cp.async.commit_group;" ::);
        }
        int buf = t & 1;
        #pragma unroll
        for (int kk = 0; kk < HBK; kk += 16) {
            u32 a[2][4];
            #pragma unroll
            for (int i = 0; i < 2; i++)
                ldm_x4(a[i], s2u(&As[buf][wr + i*16 + (lane & 15)][kk + ((lane >> 4) << 3)]));
            #pragma unroll
            for (int jj = 0; jj < 4; jj++) {
                u32 b[4];
                ldm_x4_t(b, s2u(&Bs[buf][kk + (lane & 15)][wc + jj*16 + ((lane >> 4) << 3)]));
                #pragma unroll
                for (int i = 0; i < 2; i++) {
                    mma16816(acc[i][jj*2],     a[i], b[0], b[1]);
                    mma16816(acc[i][jj*2 + 1], a[i], b[2], b[3]);
                }
            }
        }
    }

    int r1 = lane >> 2, c1 = (lane & 3) * 2;
    #pragma unroll
    for (int i = 0; i < 2; i++) {
        int gr0 = row0 + wr + i * 16 + r1;
        #pragma unroll
        for (int j = 0; j < 8; j++) {
            int gc = col0 + wc + j * 8 + c1;
            float b0 = bias[gc], b1 = bias[gc + 1];
            float v00 = acc[i][j][0] + b0, v01 = acc[i][j][1] + b1;
            float v10 = acc[i][j][2] + b0, v11 = acc[i][j][3] + b1;
            if (GELU) {
                v00 = 0.5f * v00 * (1.f + erff(v00 * 0.70710678f));
                v01 = 0.5f * v01 * (1.f + erff(v01 * 0.70710678f));
                v10 = 0.5f * v10 * (1.f + erff(v10 * 0.70710678f));
                v11 = 0.5f * v11 * (1.f + erff(v11 * 0.70710678f));
            }
            if (OUTH) {
                __half* C = (__half*)Cout;
                *(__half2*)(C + (size_t)gr0 * N + gc)       = __floats2half2_rn(v00, v01);
                *(__half2*)(C + (size_t)(gr0 + 8) * N + gc) = __floats2half2_rn(v10, v11);
            } else {
                float* C = (float*)Cout;
                *(float2*)(C + (size_t)gr0 * N + gc)       = make_float2(v00, v01);
                *(float2*)(C + (size_t)(gr0 + 8) * N + gc) = make_float2(v10, v11);
            }
        }
    }
}

// ---------------- flash attention (fp32), per (b, h, 64-row q tile) --------
#define PAD 65
__global__ __launch_bounds__(256)
void attn_kernel(const float* __restrict__ Q, const float* __restrict__ K,
                 const float* __restrict__ V, float* __restrict__ O) {
    extern __shared__ float sm[];
    float* Qs = sm;
    float* Ks = Qs + 64 * PAD;
    float* Vs = Ks + 64 * PAD;
    float* Ps = Vs + 64 * PAD;
    float* s_alpha = Ps + 64 * PAD;
    float* s_l     = s_alpha + 64;

    int tid = threadIdx.x;
    int tx = tid & 15, ty = tid >> 4;
    int qt = blockIdx.x, h = blockIdx.y, b = blockIdx.z;
    int q0 = qt * 64;
    int base = b * SS * DD + h * HD;

    for (int i = tid; i < 4096; i += 256) {
        int r = i >> 6, e = i & 63;
        Qs[e * PAD + r] = Q[base + (q0 + r) * DD + e];
    }
    float o[4][4];
    #pragma unroll
    for (int i = 0; i < 4; i++)
        #pragma unroll
        for (int j = 0; j < 4; j++) o[i][j] = 0.f;
    float m_t = -1e30f, l_t = 0.f;
    __syncthreads();

    for (int kt = 0; kt <= qt; kt++) {
        int k0 = kt * 64;
        for (int i = tid; i < 4096; i += 256) {
            int r = i >> 6, e = i & 63;
            Ks[e * PAD + r] = K[base + (k0 + r) * DD + e];
            Vs[r * PAD + e] = V[base + (k0 + r) * DD + e];
        }
        __syncthreads();

        float s[4][4];
        #pragma unroll
        for (int i = 0; i < 4; i++)
            #pragma unroll
            for (int j = 0; j < 4; j++) s[i][j] = 0.f;
        for (int d = 0; d < 64; d++) {
            float qa[4], kb[4];
            #pragma unroll
            for (int i = 0; i < 4; i++) qa[i] = Qs[d * PAD + 4 * ty + i];
            #pragma unroll
            for (int j = 0; j < 4; j++) kb[j] = Ks[d * PAD + 4 * tx + j];
            #pragma unroll
            for (int i = 0; i < 4; i++)
                #pragma unroll
                for (int j = 0; j < 4; j++)
                    s[i][j] = fmaf(qa[i], kb[j], s[i][j]);
        }
        #pragma unroll
        for (int i = 0; i < 4; i++)
            #pragma unroll
            for (int j = 0; j < 4; j++) {
                float sv = s[i][j] * 0.125f;
                if (k0 + 4 * tx + j > q0 + 4 * ty + i) sv = -1e30f;
                Ps[(4 * ty + i) * PAD + 4 * tx + j] = sv;
            }
        __syncthreads();

        if (tid < 64) {
            float mx = m_t;
            #pragma unroll 8
            for (int kk = 0; kk < 64; kk++) mx = fmaxf(mx, Ps[tid * PAD + kk]);
            float alpha = __expf(m_t - mx);
            float ssum = 0.f;
            #pragma unroll 8
            for (int kk = 0; kk < 64; kk++) {
                float p = __expf(Ps[tid * PAD + kk] - mx);
                Ps[tid * PAD + kk] = p;
                ssum += p;
            }
            l_t = l_t * alpha + ssum;
            m_t = mx;
            s_alpha[tid] = alpha;
            s_l[tid] = l_t;
        }
        __syncthreads();

        float al[4];
        #pragma unroll
        for (int i = 0; i < 4; i++) al[i] = s_alpha[4 * ty + i];
        #pragma unroll
        for (int i = 0; i < 4; i++)
            #pragma unroll
            for (int j = 0; j < 4; j++) o[i][j] *= al[i];
        for (int kk = 0; kk < 64; kk++) {
            float p[4], vv[4];
            #pragma unroll
            for (int i = 0; i < 4; i++) p[i] = Ps[(4 * ty + i) * PAD + kk];
            #pragma unroll
            for (int j = 0; j < 4; j++) vv[j] = Vs[kk * PAD + 4 * tx + j];
            #pragma unroll
            for (int i = 0; i < 4; i++)
                #pragma unroll
                for (int j = 0; j < 4; j++)
                    o[i][j] = fmaf(p[i], vv[j], o[i][j]);
        }
        __syncthreads();
    }

    float linv[4];
    #pragma unroll
    for (int i = 0; i < 4; i++) linv[i] = 1.f / s_l[4 * ty + i];
    #pragma unroll
    for (int i = 0; i < 4; i++)
        #pragma unroll
        for (int j = 0; j < 4; j++)
            O[base + (q0 + 4 * ty + i) * DD + 4 * tx + j] = o[i][j] * linv[i];
}

// ---------------- fused residual + LayerNorm --------------------------------
__inline__ __device__ float warp_sum(float v) {
    #pragma unroll
    for (int o = 16; o; o >>= 1) v += __shfl_xor_sync(0xffffffffu, v, o);
    return v;
}

__global__ __launch_bounds__(256)
void resid_ln_kernel(const float* __restrict__ a, const float* __restrict__ r,
                     const float* __restrict__ w, const float* __restrict__ bb,
                     float* __restrict__ out) {
    int row = blockIdx.x, tid = threadIdx.x;
    const float4* pa = (const float4*)(a + (size_t)row * DD);
    const float4* pr = (const float4*)(r + (size_t)row * DD);
    float4 av = pa[tid], rv = pr[tid];
    float x0 = av.x + rv.x, x1 = av.y + rv.y, x2 = av.z + rv.z, x3 = av.w + rv.w;
    float s  = x0 + x1 + x2 + x3;
    float s2 = x0*x0 + x1*x1 + x2*x2 + x3*x3;
    s = warp_sum(s);
    s2 = warp_sum(s2);
    __shared__ float sh[2][8];
    int wid = tid >> 5;
    if ((tid & 31) == 0) { sh[0][wid] = s; sh[1][wid] = s2; }
    __syncthreads();
    if (tid == 0) {
        float S = 0.f, S2 = 0.f;
        #pragma unroll
        for (int i = 0; i < 8; i++) { S += sh[0][i]; S2 += sh[1][i]; }
        sh[0][0] = S; sh[1][0] = S2;
    }
    __syncthreads();
    float mean = sh[0][0] * (1.f / DD);
    float var  = sh[1][0] * (1.f / DD) - mean * mean;
    float rstd = rsqrtf(var + 1e-5f);
    const float4* pw = (const float4*)w;
    const float4* pb = (const float4*)bb;
    float4 wv = pw[tid], bv = pb[tid];
    float4 ov;
    ov.x = (x0 - mean) * rstd * wv.x + bv.x;
    ov.y = (x1 - mean) * rstd * wv.y + bv.y;
    ov.z = (x2 - mean) * rstd * wv.z + bv.z;
    ov.w = (x3 - mean) * rstd * wv.w + bv.w;
    ((float4*)(out + (size_t)row * DD))[tid] = ov;
}

__global__ void copy_kernel(const float* __restrict__ src, float* __restrict__ dst) {
    int i = blockIdx.x * 256 + threadIdx.x;
    ((float4*)dst)[i] = ((const float4*)src)[i];
}

// ---------------- host ------------------------------------------------------
extern "C" void kernel_launch(void* const* d_in, const int* in_sizes, int n_in,
                              void* d_out, int out_size) {
    const void*  x    = d_in[0];
    const float* tok  = (const float*)d_in[1];
    const float* pos  = (const float*)d_in[2];
    const float* Wq   = (const float*)d_in[3];
    const float* bq   = (const float*)d_in[4];
    const float* Wk   = (const float*)d_in[5];
    const float* bk   = (const float*)d_in[6];
    const float* Wv   = (const float*)d_in[7];
    const float* bv   = (const float*)d_in[8];
    const float* Wo   = (const float*)d_in[9];
    const float* bo   = (const float*)d_in[10];
    const float* ln1w = (const float*)d_in[11];
    const float* ln1b = (const float*)d_in[12];
    const float* ln2w = (const float*)d_in[13];
    const float* ln2b = (const float*)d_in[14];
    const float* W1   = (const float*)d_in[15];
    const float* b1   = (const float*)d_in[16];
    const float* W2   = (const float*)d_in[17];
    const float* b2   = (const float*)d_in[18];
    const float* Wout = (const float*)d_in[19];
    const float* bout = (const float*)d_in[20];
    float* out = (float*)d_out;

    float *h = 0, *q = 0, *k = 0, *v = 0, *attn = 0, *tmp = 0;
    __half *a16 = 0, *ff16 = 0, *wq16 = 0, *wk16 = 0, *wv16 = 0, *wo16 = 0;
    __half *w1h = 0, *w2h = 0, *wouth = 0;
    int* flag = 0;
    cudaGetSymbolAddress((void**)&h,     g_h);
    cudaGetSymbolAddress((void**)&q,     g_q);
    cudaGetSymbolAddress((void**)&k,     g_k);
    cudaGetSymbolAddress((void**)&v,     g_v);
    cudaGetSymbolAddress((void**)&attn,  g_attn);
    cudaGetSymbolAddress((void**)&tmp,   g_tmp);
    cudaGetSymbolAddress((void**)&a16,   g_a16);
    cudaGetSymbolAddress((void**)&ff16,  g_ff16);
    cudaGetSymbolAddress((void**)&wq16,  g_wq16);
    cudaGetSymbolAddress((void**)&wk16,  g_wk16);
    cudaGetSymbolAddress((void**)&wv16,  g_wv16);
    cudaGetSymbolAddress((void**)&wo16,  g_wo16);
    cudaGetSymbolAddress((void**)&w1h,   g_w1h);
    cudaGetSymbolAddress((void**)&w2h,   g_w2h);
    cudaGetSymbolAddress((void**)&wouth, g_wouth);
    cudaGetSymbolAddress((void**)&flag,  g_flag);

    const int smem_attn = 4 * 64 * PAD * 4 + 2 * 64 * 4;
    cudaFuncSetAttribute(attn_kernel, cudaFuncAttributeMaxDynamicSharedMemorySize, smem_attn);

    detect_kernel<<<1, 256>>>((const int*)x, flag);
    embed_kernel<<<TT, 256>>>(x, tok, pos, h, flag);
    f2h_kernel<<<(DD * VV / 4 + 255) / 256, 256>>>(Wout, wouth, DD * VV / 4);

    dim3 gD(DD / HBN, TT / HBM);
    dim3 gF(FF / HBN, TT / HBM);
    dim3 gV(VV / HBN, TT / HBM);

    for (int l = 0; l < LL; l++) {
        size_t woff = (size_t)l * HH * DD * HD;
        repack_kernel<<<DD * DD / 256, 256>>>(Wq + woff, wq16);
        repack_kernel<<<DD * DD / 256, 256>>>(Wk + woff, wk16);
        repack_kernel<<<DD * DD / 256, 256>>>(Wv + woff, wv16);
        f2h_kernel<<<DD * DD / 1024, 256>>>(Wo + (size_t)l * DD * DD, wo16, DD * DD / 4);
        f2h_kernel<<<DD * FF / 1024, 256>>>(W1 + (size_t)l * DD * FF, w1h, DD * FF / 4);
        f2h_kernel<<<FF * DD / 1024, 256>>>(W2 + (size_t)l * FF * DD, w2h, FF * DD / 4);

        f2h_kernel<<<TT * DD / 1024, 256>>>(h, a16, TT * DD / 4);
        hgemm_kernel<false, false><<<gD, 256>>>(a16, wq16, bq + l * DD, q, TT, DD, DD);
        hgemm_kernel<false, false><<<gD, 256>>>(a16, wk16, bk + l * DD, k, TT, DD, DD);
        hgemm_kernel<false, false><<<gD, 256>>>(a16, wv16, bv + l * DD, v, TT, DD, DD);

        dim3 ga(SS / 64, HH, BB);
        attn_kernel<<<ga, 256, smem_attn>>>(q, k, v, attn);

        f2h_kernel<<<TT * DD / 1024, 256>>>(attn, a16, TT * DD / 4);
        hgemm_kernel<false, false><<<gD, 256>>>(a16, wo16, bo + l * DD, tmp, TT, DD, DD);
        resid_ln_kernel<<<TT, 256>>>(h, tmp, ln1w + l * DD, ln1b + l * DD, h);

        f2h_kernel<<<TT * DD / 1024, 256>>>(h, a16, TT * DD / 4);
        hgemm_kernel<true, true><<<gF, 256>>>(a16, w1h, b1 + l * FF, ff16, TT, FF, DD);
        hgemm_kernel<false, false><<<gD, 256>>>(ff16, w2h, b2 + l * DD, tmp, TT, DD, FF);
        resid_ln_kernel<<<TT, 256>>>(h, tmp, ln2w + l * DD, ln2b + l * DD, h);
    }

    f2h_kernel<<<TT * DD / 1024, 256>>>(h, a16, TT * DD / 4);
    hgemm_kernel<false, false><<<gV, 256>>>(a16, wouth, bout, out, TT, VV, DD);
    copy_kernel<<<TT * DD / 4 / 256, 256>>>(h, out + (size_t)TT * VV);
}

// round 5
// speedup vs baseline: 5.1685x; 1.3497x over previous
#include <cuda_runtime.h>
#include <cuda_fp16.h>
#include <cstdint>
#include <math.h>

typedef unsigned int u32;

#define BB 4
#define SS 1024
#define DD 1024
#define HH 16
#define HD 64
#define FF 4096
#define VV 32000
#define LL 2
#define TT (BB*SS)

// scratch (device globals: allocation is forbidden)
__device__ float  g_h[TT*DD];
__device__ float  g_tmp[TT*DD];
__device__ __half g_h16[TT*DD];
__device__ __half g_q16[TT*DD];
__device__ __half g_k16[TT*DD];
__device__ __half g_v16[TT*DD];
__device__ __half g_attn16[TT*DD];
__device__ __half g_ff16[(size_t)TT*FF];
__device__ __half g_wq16[DD*DD];
__device__ __half g_wk16[DD*DD];
__device__ __half g_wv16[DD*DD];
__device__ __half g_wo16[DD*DD];
__device__ __half g_w1h[(size_t)DD*FF];
__device__ __half g_w2h[(size_t)FF*DD];
__device__ __half g_wouth[(size_t)DD*VV];
__device__ int    g_flag[1];

// ---------------- helpers ---------------------------------------------------
__device__ __forceinline__ void ldm_x4(u32* r, u32 addr) {
    asm volatile("ldmatrix.sync.aligned.m8n8.x4.shared.b16 {%0,%1,%2,%3}, [%4];"
        : "=r"(r[0]), "=r"(r[1]), "=r"(r[2]), "=r"(r[3]) : "r"(addr));
}
__device__ __forceinline__ void ldm_x4_t(u32* r, u32 addr) {
    asm volatile("ldmatrix.sync.aligned.m8n8.x4.trans.shared.b16 {%0,%1,%2,%3}, [%4];"
        : "=r"(r[0]), "=r"(r[1]), "=r"(r[2]), "=r"(r[3]) : "r"(addr));
}
__device__ __forceinline__ void mma16816(float* d, const u32* a, u32 b0, u32 b1) {
    asm volatile("mma.sync.aligned.m16n8k16.row.col.f32.f16.f16.f32 "
        "{%0,%1,%2,%3}, {%4,%5,%6,%7}, {%8,%9}, {%0,%1,%2,%3};"
        : "+f"(d[0]), "+f"(d[1]), "+f"(d[2]), "+f"(d[3])
        : "r"(a[0]), "r"(a[1]), "r"(a[2]), "r"(a[3]), "r"(b0), "r"(b1));
}
__device__ __forceinline__ void cpa16(u32 s, const void* g) {
    asm volatile("cp.async.cg.shared.global [%0], [%1], 16;" :: "r"(s), "l"(g));
}
__device__ __forceinline__ u32 s2u(const void* p) {
    return (u32)__cvta_generic_to_shared(p);
}
__device__ __forceinline__ u32 packh2(float a, float b) {
    __half2 hv = __floats2half2_rn(a, b);
    return *(u32*)&hv;
}

// token dtype sniffer
__global__ void detect_kernel(const int* __restrict__ x32, int* __restrict__ flag) {
    __shared__ int sh;
    if (threadIdx.x == 0) sh = 0;
    __syncthreads();
    int acc = 0;
    for (int i = threadIdx.x; i < TT/2; i += blockDim.x) acc |= x32[2*i + 1];
    #pragma unroll
    for (int o = 16; o; o >>= 1) acc |= __shfl_xor_sync(0xffffffffu, acc, o);
    if ((threadIdx.x & 31) == 0) atomicOr(&sh, acc);
    __syncthreads();
    if (threadIdx.x == 0) *flag = (sh != 0) ? 1 : 0;
}

__global__ void embed_kernel(const void* __restrict__ x,
                             const float* __restrict__ tok,
                             const float* __restrict__ pos,
                             float* __restrict__ h, __half* __restrict__ h16,
                             const int* __restrict__ flag) {
    int t = blockIdx.x;
    int idx;
    if (*flag) idx = ((const int*)x)[t];
    else       idx = (int)(((const long long*)x)[t]);
    int s = t & (SS - 1);
    const float4* tp = (const float4*)(tok + (size_t)idx * DD);
    const float4* pp = (const float4*)(pos + (size_t)s * DD);
    int i = threadIdx.x;
    float4 a = tp[i], b = pp[i];
    float4 r = make_float4(a.x + b.x, a.y + b.y, a.z + b.z, a.w + b.w);
    ((float4*)(h + (size_t)t * DD))[i] = r;
    __half2* hp = (__half2*)(h16 + (size_t)t * DD);
    hp[2*i]     = __floats2half2_rn(r.x, r.y);
    hp[2*i + 1] = __floats2half2_rn(r.z, r.w);
}

// repack [H][D][HD] -> [D][H*HD] fp16
__global__ void repack_kernel(const float* __restrict__ src, __half* __restrict__ dst) {
    int i = blockIdx.x * 256 + threadIdx.x;
    int d  = i >> 10;
    int he = i & 1023;
    int hh = he >> 6;
    int e  = he & 63;
    dst[i] = __float2half(src[((size_t)(hh << 10) + d) * HD + e]);
}

__global__ void f2h_kernel(const float* __restrict__ src, __half* __restrict__ dst,
                           int n4) {
    int i = blockIdx.x * 256 + threadIdx.x;
    if (i >= n4) return;
    float4 v = ((const float4*)src)[i];
    ((__half2*)dst)[2*i]     = __floats2half2_rn(v.x, v.y);
    ((__half2*)dst)[2*i + 1] = __floats2half2_rn(v.z, v.w);
}

// ---------------- fp16 tensor-core GEMM ------------------------------------
#define HBM 128
#define HBN 128
#define HBK 32
#define APAD 8
#define BPAD 8

template<bool GELU, bool OUTH>
__global__ __launch_bounds__(256)
void hgemm_kernel(const __half* __restrict__ A, const __half* __restrict__ B,
                  const float* __restrict__ bias, void* __restrict__ Cout,
                  int M, int N, int K) {
    __shared__ __half As[2][HBM][HBK + APAD];
    __shared__ __half Bs[2][HBK][HBN + BPAD];

    int tid = threadIdx.x;
    int lane = tid & 31, warp = tid >> 5;
    int row0 = blockIdx.y * HBM;
    int col0 = blockIdx.x * HBN;
    int wr = (warp & 3) * 32;
    int wc = (warp >> 2) * 64;

    int arow = tid >> 1, acol = (tid & 1) * 16;
    int brow = tid >> 3, bcol = (tid & 7) * 16;
    const __half* Ag = A + (size_t)(row0 + arow) * K + acol;
    const __half* Bg = B + (size_t)brow * N + col0 + bcol;

    u32 sA0 = s2u(&As[0][arow][acol]);
    u32 sA1 = s2u(&As[1][arow][acol]);
    u32 sB0 = s2u(&Bs[0][brow][bcol]);
    u32 sB1 = s2u(&Bs[1][brow][bcol]);

    float acc[2][8][4];
    #pragma unroll
    for (int i = 0; i < 2; i++)
        #pragma unroll
        for (int j = 0; j < 8; j++)
            #pragma unroll
            for (int c = 0; c < 4; c++) acc[i][j][c] = 0.f;

    int nk = K / HBK;
    cpa16(sA0, Ag);       cpa16(sA0 + 16, Ag + 8);
    cpa16(sB0, Bg);       cpa16(sB0 + 16, Bg + 8);
    asm volatile("cp.async.commit_group;" ::);

    for (int t = 0; t < nk; t++) {
        asm volatile("cp.async.wait_group 0;" ::);
        __syncthreads();
        if (t + 1 < nk) {
            u32 sa = ((t + 1) & 1) ? sA1 : sA0;
            u32 sb = ((t + 1) & 1) ? sB1 : sB0;
            const __half* ag = Ag + (size_t)(t + 1) * HBK;
            const __half* bg = Bg + (size_t)(t + 1) * HBK * N;
            cpa16(sa, ag);       cpa16(sa + 16, ag + 8);
            cpa16(sb, bg);       cpa16(sb + 16, bg + 8);
            asm volatile("cp.async.commit_group;" ::);
        }
        int buf = t & 1;
        #pragma unroll
        for (int kk = 0; kk < HBK; kk += 16) {
            u32 a[2][4];
            #pragma unroll
            for (int i = 0; i < 2; i++)
                ldm_x4(a[i], s2u(&As[buf][wr + i*16 + (lane & 15)][kk + ((lane >> 4) << 3)]));
            #pragma unroll
            for (int jj = 0; jj < 4; jj++) {
                u32 b[4];
                ldm_x4_t(b, s2u(&Bs[buf][kk + (lane & 15)][wc + jj*16 + ((lane >> 4) << 3)]));
                #pragma unroll
                for (int i = 0; i < 2; i++) {
                    mma16816(acc[i][jj*2],     a[i], b[0], b[1]);
                    mma16816(acc[i][jj*2 + 1], a[i], b[2], b[3]);
                }
            }
        }
    }

    int r1 = lane >> 2, c1 = (lane & 3) * 2;
    #pragma unroll
    for (int i = 0; i < 2; i++) {
        int gr0 = row0 + wr + i * 16 + r1;
        #pragma unroll
        for (int j = 0; j < 8; j++) {
            int gc = col0 + wc + j * 8 + c1;
            float b0 = bias[gc], b1 = bias[gc + 1];
            float v00 = acc[i][j][0] + b0, v01 = acc[i][j][1] + b1;
            float v10 = acc[i][j][2] + b0, v11 = acc[i][j][3] + b1;
            if (GELU) {
                v00 = 0.5f * v00 * (1.f + erff(v00 * 0.70710678f));
                v01 = 0.5f * v01 * (1.f + erff(v01 * 0.70710678f));
                v10 = 0.5f * v10 * (1.f + erff(v10 * 0.70710678f));
                v11 = 0.5f * v11 * (1.f + erff(v11 * 0.70710678f));
            }
            if (OUTH) {
                __half* C = (__half*)Cout;
                *(__half2*)(C + (size_t)gr0 * N + gc)       = __floats2half2_rn(v00, v01);
                *(__half2*)(C + (size_t)(gr0 + 8) * N + gc) = __floats2half2_rn(v10, v11);
            } else {
                float* C = (float*)Cout;
                *(float2*)(C + (size_t)gr0 * N + gc)       = make_float2(v00, v01);
                *(float2*)(C + (size_t)(gr0 + 8) * N + gc) = make_float2(v10, v11);
            }
        }
    }
}

// ---------------- fp16 tensor-core flash attention -------------------------
// grid (SS/64, HH, BB), 128 threads (4 warps); warp w owns q rows 16w..16w+15.
#define AP 72   // padded row length in halfs (144B rows: conflict-free ldmatrix)

__global__ __launch_bounds__(128)
void fattn_kernel(const __half* __restrict__ Q, const __half* __restrict__ K,
                  const __half* __restrict__ V, __half* __restrict__ O) {
    __shared__ __half Qs[64][AP];
    __shared__ __half Ks[2][64][AP];
    __shared__ __half Vs[2][64][AP];

    int tid = threadIdx.x, lane = tid & 31, warp = tid >> 5;
    int qt = blockIdx.x, h = blockIdx.y, b = blockIdx.z;
    int q0 = qt * 64;
    size_t base = (size_t)b * SS * DD + h * HD;

    // prologue: Q tile + K/V tile 0 in one cp.async group
    for (int i = tid; i < 512; i += 128) {
        int r = i >> 3, c8 = (i & 7) * 8;
        cpa16(s2u(&Qs[r][c8]),    Q + base + (size_t)(q0 + r) * DD + c8);
        cpa16(s2u(&Ks[0][r][c8]), K + base + (size_t)r * DD + c8);
        cpa16(s2u(&Vs[0][r][c8]), V + base + (size_t)r * DD + c8);
    }
    asm volatile("cp.async.commit_group;" ::);
    asm volatile("cp.async.wait_group 0;" ::);
    __syncthreads();

    // Q fragments: 16 rows x 64 hd per warp
    u32 qf[4][4];
    #pragma unroll
    for (int kc = 0; kc < 4; kc++)
        ldm_x4(qf[kc], s2u(&Qs[warp*16 + (lane & 15)][kc*16 + ((lane >> 4) << 3)]));

    float o[8][4];
    #pragma unroll
    for (int j = 0; j < 8; j++)
        #pragma unroll
        for (int c = 0; c < 4; c++) o[j][c] = 0.f;
    float m0 = -1e30f, m1 = -1e30f, l0 = 0.f, l1 = 0.f;

    int r0 = lane >> 2;
    int rowg0 = q0 + warp * 16 + r0;
    int rowg1 = rowg0 + 8;

    for (int kt = 0; kt <= qt; kt++) {
        int buf = kt & 1;
        if (kt > 0) {
            asm volatile("cp.async.wait_group 0;" ::);
            __syncthreads();
        }
        if (kt < qt) {
            int nb = buf ^ 1;
            size_t kb = base + (size_t)(kt + 1) * 64 * DD;
            for (int i = tid; i < 512; i += 128) {
                int r = i >> 3, c8 = (i & 7) * 8;
                cpa16(s2u(&Ks[nb][r][c8]), K + kb + (size_t)r * DD + c8);
                cpa16(s2u(&Vs[nb][r][c8]), V + kb + (size_t)r * DD + c8);
            }
            asm volatile("cp.async.commit_group;" ::);
        }

        // S = Q K^T  (16 x 64 per warp)
        float s[8][4];
        #pragma unroll
        for (int j = 0; j < 8; j++)
            #pragma unroll
            for (int c = 0; c < 4; c++) s[j][c] = 0.f;
        #pragma unroll
        for (int kc = 0; kc < 4; kc++) {
            #pragma unroll
            for (int kg = 0; kg < 4; kg++) {
                u32 kb4[4];
                ldm_x4(kb4, s2u(&Ks[buf][kg*16 + (lane & 15)][kc*16 + ((lane >> 4) << 3)]));
                mma16816(s[kg*2],     qf[kc], kb4[0], kb4[2]);
                mma16816(s[kg*2 + 1], qf[kc], kb4[1], kb4[3]);
            }
        }

        // scale + causal mask + row max
        int colb = kt * 64 + (lane & 3) * 2;
        float ml0 = -1e30f, ml1 = -1e30f;
        #pragma unroll
        for (int j = 0; j < 8; j++) {
            int c0 = colb + j * 8, c1 = c0 + 1;
            s[j][0] = (c0 <= rowg0) ? s[j][0] * 0.125f : -1e30f;
            s[j][1] = (c1 <= rowg0) ? s[j][1] * 0.125f : -1e30f;
            s[j][2] = (c0 <= rowg1) ? s[j][2] * 0.125f : -1e30f;
            s[j][3] = (c1 <= rowg1) ? s[j][3] * 0.125f : -1e30f;
            ml0 = fmaxf(ml0, fmaxf(s[j][0], s[j][1]));
            ml1 = fmaxf(ml1, fmaxf(s[j][2], s[j][3]));
        }
        ml0 = fmaxf(ml0, __shfl_xor_sync(0xffffffffu, ml0, 1));
        ml0 = fmaxf(ml0, __shfl_xor_sync(0xffffffffu, ml0, 2));
        ml1 = fmaxf(ml1, __shfl_xor_sync(0xffffffffu, ml1, 1));
        ml1 = fmaxf(ml1, __shfl_xor_sync(0xffffffffu, ml1, 2));
        float mn0 = fmaxf(m0, ml0), mn1 = fmaxf(m1, ml1);
        float al0 = __expf(m0 - mn0), al1 = __expf(m1 - mn1);

        // exp, pack P as A-fragments, partial row sums
        u32 pf[4][4];
        float la0 = 0.f, la1 = 0.f;
        #pragma unroll
        for (int j = 0; j < 8; j++) {
            float p0 = __expf(s[j][0] - mn0), p1 = __expf(s[j][1] - mn0);
            float p2 = __expf(s[j][2] - mn1), p3 = __expf(s[j][3] - mn1);
            la0 += p0 + p1;
            la1 += p2 + p3;
            int kc = j >> 1;
            if ((j & 1) == 0) {
                pf[kc][0] = packh2(p0, p1);
                pf[kc][1] = packh2(p2, p3);
            } else {
                pf[kc][2] = packh2(p0, p1);
                pf[kc][3] = packh2(p2, p3);
            }
        }
        la0 += __shfl_xor_sync(0xffffffffu, la0, 1);
        la0 += __shfl_xor_sync(0xffffffffu, la0, 2);
        la1 += __shfl_xor_sync(0xffffffffu, la1, 1);
        la1 += __shfl_xor_sync(0xffffffffu, la1, 2);
        l0 = l0 * al0 + la0;
        l1 = l1 * al1 + la1;
        m0 = mn0; m1 = mn1;

        // rescale O, then O += P V
        #pragma unroll
        for (int j = 0; j < 8; j++) {
            o[j][0] *= al0; o[j][1] *= al0;
            o[j][2] *= al1; o[j][3] *= al1;
        }
        #pragma unroll
        for (int kc = 0; kc < 4; kc++) {
            #pragma unroll
            for (int nn = 0; nn < 4; nn++) {
                u32 vb[4];
                ldm_x4_t(vb, s2u(&Vs[buf][kc*16 + (lane & 15)][nn*16 + ((lane >> 4) << 3)]));
                mma16816(o[nn*2],     pf[kc], vb[0], vb[1]);
                mma16816(o[nn*2 + 1], pf[kc], vb[2], vb[3]);
            }
        }
    }

    float il0 = 1.f / l0, il1 = 1.f / l1;
    size_t ob = (size_t)(b * SS + q0 + warp * 16 + r0) * DD + h * HD;
    #pragma unroll
    for (int j = 0; j < 8; j++) {
        int col = j * 8 + (lane & 3) * 2;
        *(__half2*)(O + ob + col)        = __floats2half2_rn(o[j][0]*il0, o[j][1]*il0);
        *(__half2*)(O + ob + 8*DD + col) = __floats2half2_rn(o[j][2]*il1, o[j][3]*il1);
    }
}

// ---------------- fused residual + LayerNorm (dual output) ------------------
__inline__ __device__ float warp_sum(float v) {
    #pragma unroll
    for (int o = 16; o; o >>= 1) v += __shfl_xor_sync(0xffffffffu, v, o);
    return v;
}

__global__ __launch_bounds__(256)
void resid_ln_kernel(const float* __restrict__ a, const float* __restrict__ r,
                     const float* __restrict__ w, const float* __restrict__ bb,
                     float* __restrict__ out, __half* __restrict__ out16) {
    int row = blockIdx.x, tid = threadIdx.x;
    const float4* pa = (const float4*)(a + (size_t)row * DD);
    const float4* pr = (const float4*)(r + (size_t)row * DD);
    float4 av = pa[tid], rv = pr[tid];
    float x0 = av.x + rv.x, x1 = av.y + rv.y, x2 = av.z + rv.z, x3 = av.w + rv.w;
    float s  = x0 + x1 + x2 + x3;
    float s2 = x0*x0 + x1*x1 + x2*x2 + x3*x3;
    s = warp_sum(s);
    s2 = warp_sum(s2);
    __shared__ float sh[2][8];
    int wid = tid >> 5;
    if ((tid & 31) == 0) { sh[0][wid] = s; sh[1][wid] = s2; }
    __syncthreads();
    if (tid == 0) {
        float S = 0.f, S2 = 0.f;
        #pragma unroll
        for (int i = 0; i < 8; i++) { S += sh[0][i]; S2 += sh[1][i]; }
        sh[0][0] = S; sh[1][0] = S2;
    }
    __syncthreads();
    float mean = sh[0][0] * (1.f / DD);
    float var  = sh[1][0] * (1.f / DD) - mean * mean;
    float rstd = rsqrtf(var + 1e-5f);
    const float4* pw = (const float4*)w;
    const float4* pb = (const float4*)bb;
    float4 wv = pw[tid], bv = pb[tid];
    float4 ov;
    ov.x = (x0 - mean) * rstd * wv.x + bv.x;
    ov.y = (x1 - mean) * rstd * wv.y + bv.y;
    ov.z = (x2 - mean) * rstd * wv.z + bv.z;
    ov.w = (x3 - mean) * rstd * wv.w + bv.w;
    ((float4*)(out + (size_t)row * DD))[tid] = ov;
    __half2* o16 = (__half2*)(out16 + (size_t)row * DD);
    o16[2*tid]     = __floats2half2_rn(ov.x, ov.y);
    o16[2*tid + 1] = __floats2half2_rn(ov.z, ov.w);
}

__global__ void copy_kernel(const float* __restrict__ src, float* __restrict__ dst) {
    int i = blockIdx.x * 256 + threadIdx.x;
    ((float4*)dst)[i] = ((const float4*)src)[i];
}

// ---------------- host ------------------------------------------------------
extern "C" void kernel_launch(void* const* d_in, const int* in_sizes, int n_in,
                              void* d_out, int out_size) {
    const void*  x    = d_in[0];
    const float* tok  = (const float*)d_in[1];
    const float* pos  = (const float*)d_in[2];
    const float* Wq   = (const float*)d_in[3];
    const float* bq   = (const float*)d_in[4];
    const float* Wk   = (const float*)d_in[5];
    const float* bk   = (const float*)d_in[6];
    const float* Wv   = (const float*)d_in[7];
    const float* bv   = (const float*)d_in[8];
    const float* Wo   = (const float*)d_in[9];
    const float* bo   = (const float*)d_in[10];
    const float* ln1w = (const float*)d_in[11];
    const float* ln1b = (const float*)d_in[12];
    const float* ln2w = (const float*)d_in[13];
    const float* ln2b = (const float*)d_in[14];
    const float* W1   = (const float*)d_in[15];
    const float* b1   = (const float*)d_in[16];
    const float* W2   = (const float*)d_in[17];
    const float* b2   = (const float*)d_in[18];
    const float* Wout = (const float*)d_in[19];
    const float* bout = (const float*)d_in[20];
    float* out = (float*)d_out;

    float *h = 0, *tmp = 0;
    __half *h16 = 0, *q16 = 0, *k16 = 0, *v16 = 0, *attn16 = 0, *ff16 = 0;
    __half *wq16 = 0, *wk16 = 0, *wv16 = 0, *wo16 = 0, *w1h = 0, *w2h = 0, *wouth = 0;
    int* flag = 0;
    cudaGetSymbolAddress((void**)&h,      g_h);
    cudaGetSymbolAddress((void**)&tmp,    g_tmp);
    cudaGetSymbolAddress((void**)&h16,    g_h16);
    cudaGetSymbolAddress((void**)&q16,    g_q16);
    cudaGetSymbolAddress((void**)&k16,    g_k16);
    cudaGetSymbolAddress((void**)&v16,    g_v16);
    cudaGetSymbolAddress((void**)&attn16, g_attn16);
    cudaGetSymbolAddress((void**)&ff16,   g_ff16);
    cudaGetSymbolAddress((void**)&wq16,   g_wq16);
    cudaGetSymbolAddress((void**)&wk16,   g_wk16);
    cudaGetSymbolAddress((void**)&wv16,   g_wv16);
    cudaGetSymbolAddress((void**)&wo16,   g_wo16);
    cudaGetSymbolAddress((void**)&w1h,    g_w1h);
    cudaGetSymbolAddress((void**)&w2h,    g_w2h);
    cudaGetSymbolAddress((void**)&wouth,  g_wouth);
    cudaGetSymbolAddress((void**)&flag,   g_flag);

    detect_kernel<<<1, 256>>>((const int*)x, flag);
    embed_kernel<<<TT, 256>>>(x, tok, pos, h, h16, flag);
    f2h_kernel<<<(DD * VV / 4 + 255) / 256, 256>>>(Wout, wouth, DD * VV / 4);

    dim3 gD(DD / HBN, TT / HBM);
    dim3 gF(FF / HBN, TT / HBM);
    dim3 gV(VV / HBN, TT / HBM);

    for (int l = 0; l < LL; l++) {
        size_t woff = (size_t)l * HH * DD * HD;
        repack_kernel<<<DD * DD / 256, 256>>>(Wq + woff, wq16);
        repack_kernel<<<DD * DD / 256, 256>>>(Wk + woff, wk16);
        repack_kernel<<<DD * DD / 256, 256>>>(Wv + woff, wv16);
        f2h_kernel<<<DD * DD / 1024, 256>>>(Wo + (size_t)l * DD * DD, wo16, DD * DD / 4);
        f2h_kernel<<<DD * FF / 1024, 256>>>(W1 + (size_t)l * DD * FF, w1h, DD * FF / 4);
        f2h_kernel<<<FF * DD / 1024, 256>>>(W2 + (size_t)l * FF * DD, w2h, FF * DD / 4);

        hgemm_kernel<false, true><<<gD, 256>>>(h16, wq16, bq + l * DD, q16, TT, DD, DD);
        hgemm_kernel<false, true><<<gD, 256>>>(h16, wk16, bk + l * DD, k16, TT, DD, DD);
        hgemm_kernel<false, true><<<gD, 256>>>(h16, wv16, bv + l * DD, v16, TT, DD, DD);

        dim3 ga(SS / 64, HH, BB);
        fattn_kernel<<<ga, 128>>>(q16, k16, v16, attn16);

        hgemm_kernel<false, false><<<gD, 256>>>(attn16, wo16, bo + l * DD, tmp, TT, DD, DD);
        resid_ln_kernel<<<TT, 256>>>(h, tmp, ln1w + l * DD, ln1b + l * DD, h, h16);

        hgemm_kernel<true, true><<<gF, 256>>>(h16, w1h, b1 + l * FF, ff16, TT, FF, DD);
        hgemm_kernel<false, false><<<gD, 256>>>(ff16, w2h, b2 + l * DD, tmp, TT, DD, FF);
        resid_ln_kernel<<<TT, 256>>>(h, tmp, ln2w + l * DD, ln2b + l * DD, h, h16);
    }

    hgemm_kernel<false, false><<<gV, 256>>>(h16, wouth, bout, out, TT, VV, DD);
    copy_kernel<<<TT * DD / 4 / 256, 256>>>(h, out + (size_t)TT * VV);
}

// round 16
// speedup vs baseline: 5.3884x; 1.0425x over previous
#include <cuda_runtime.h>
#include <cuda_fp16.h>
#include <cstdint>
#include <math.h>

typedef unsigned int u32;

#define BB 4
#define SS 1024
#define DD 1024
#define HH 16
#define HD 64
#define FF 4096
#define VV 32000
#define LL 2
#define TT (BB*SS)

// scratch (device globals: allocation is forbidden)
__device__ float  g_h[TT*DD];
__device__ float  g_tmp[TT*DD];
__device__ __half g_h16[TT*DD];
__device__ __half g_q16[TT*DD];
__device__ __half g_k16[TT*DD];
__device__ __half g_v16[TT*DD];
__device__ __half g_attn16[TT*DD];
__device__ __half g_ff16[(size_t)TT*FF];
__device__ __half g_wq16[DD*DD];
__device__ __half g_wk16[DD*DD];
__device__ __half g_wv16[DD*DD];
__device__ __half g_wo16[DD*DD];
__device__ __half g_w1h[(size_t)DD*FF];
__device__ __half g_w2h[(size_t)FF*DD];
__device__ __half g_wouth[(size_t)DD*VV];
__device__ int    g_flag[1];

// ---------------- helpers ---------------------------------------------------
__device__ __forceinline__ void ldm_x4(u32* r, u32 addr) {
    asm volatile("ldmatrix.sync.aligned.m8n8.x4.shared.b16 {%0,%1,%2,%3}, [%4];"
        : "=r"(r[0]), "=r"(r[1]), "=r"(r[2]), "=r"(r[3]) : "r"(addr));
}
__device__ __forceinline__ void ldm_x4_t(u32* r, u32 addr) {
    asm volatile("ldmatrix.sync.aligned.m8n8.x4.trans.shared.b16 {%0,%1,%2,%3}, [%4];"
        : "=r"(r[0]), "=r"(r[1]), "=r"(r[2]), "=r"(r[3]) : "r"(addr));
}
__device__ __forceinline__ void mma16816(float* d, const u32* a, u32 b0, u32 b1) {
    asm volatile("mma.sync.aligned.m16n8k16.row.col.f32.f16.f16.f32 "
        "{%0,%1,%2,%3}, {%4,%5,%6,%7}, {%8,%9}, {%0,%1,%2,%3};"
        : "+f"(d[0]), "+f"(d[1]), "+f"(d[2]), "+f"(d[3])
        : "r"(a[0]), "r"(a[1]), "r"(a[2]), "r"(a[3]), "r"(b0), "r"(b1));
}
__device__ __forceinline__ void cpa16(u32 s, const void* g) {
    asm volatile("cp.async.cg.shared.global [%0], [%1], 16;" :: "r"(s), "l"(g));
}
__device__ __forceinline__ u32 s2u(const void* p) {
    return (u32)__cvta_generic_to_shared(p);
}
__device__ __forceinline__ u32 packh2(float a, float b) {
    __half2 hv = __floats2half2_rn(a, b);
    return *(u32*)&hv;
}

// token dtype sniffer
__global__ void detect_kernel(const int* __restrict__ x32, int* __restrict__ flag) {
    __shared__ int sh;
    if (threadIdx.x == 0) sh = 0;
    __syncthreads();
    int acc = 0;
    for (int i = threadIdx.x; i < TT/2; i += blockDim.x) acc |= x32[2*i + 1];
    #pragma unroll
    for (int o = 16; o; o >>= 1) acc |= __shfl_xor_sync(0xffffffffu, acc, o);
    if ((threadIdx.x & 31) == 0) atomicOr(&sh, acc);
    __syncthreads();
    if (threadIdx.x == 0) *flag = (sh != 0) ? 1 : 0;
}

__global__ void embed_kernel(const void* __restrict__ x,
                             const float* __restrict__ tok,
                             const float* __restrict__ pos,
                             float* __restrict__ h, __half* __restrict__ h16,
                             const int* __restrict__ flag) {
    int t = blockIdx.x;
    int idx;
    if (*flag) idx = ((const int*)x)[t];
    else       idx = (int)(((const long long*)x)[t]);
    int s = t & (SS - 1);
    const float4* tp = (const float4*)(tok + (size_t)idx * DD);
    const float4* pp = (const float4*)(pos + (size_t)s * DD);
    int i = threadIdx.x;
    float4 a = tp[i], b = pp[i];
    float4 r = make_float4(a.x + b.x, a.y + b.y, a.z + b.z, a.w + b.w);
    ((float4*)(h + (size_t)t * DD))[i] = r;
    __half2* hp = (__half2*)(h16 + (size_t)t * DD);
    hp[2*i]     = __floats2half2_rn(r.x, r.y);
    hp[2*i + 1] = __floats2half2_rn(r.z, r.w);
}

// repack [H][D][HD] -> [D][H*HD] fp16
__global__ void repack_kernel(const float* __restrict__ src, __half* __restrict__ dst) {
    int i = blockIdx.x * 256 + threadIdx.x;
    int d  = i >> 10;
    int he = i & 1023;
    int hh = he >> 6;
    int e  = he & 63;
    dst[i] = __float2half(src[((size_t)(hh << 10) + d) * HD + e]);
}

__global__ void f2h_kernel(const float* __restrict__ src, __half* __restrict__ dst,
                           int n4) {
    int i = blockIdx.x * 256 + threadIdx.x;
    if (i >= n4) return;
    float4 v = ((const float4*)src)[i];
    ((__half2*)dst)[2*i]     = __floats2half2_rn(v.x, v.y);
    ((__half2*)dst)[2*i + 1] = __floats2half2_rn(v.z, v.w);
}

// ---------------- fp16 mma GEMM: 256x128x32, 3-stage cp.async --------------
// C[M,N] = A[M,K](f16) * B[K,N](f16) + bias, optional GELU, f32/f16 out.
#define GBM 256
#define GBN 128
#define GBK 32
#define APITCH 40    // halfs per A smem row
#define BPITCH 136   // halfs per B smem row
#define A_ST_BYTES (GBM * APITCH * 2)          // 20480
#define B_ST_BYTES (GBK * BPITCH * 2)          // 8704
#define ST_BYTES   (A_ST_BYTES + B_ST_BYTES)   // 29184
#define G_SMEM     (3 * ST_BYTES)              // 87552

template<bool GELU, bool OUTH>
__global__ __launch_bounds__(256)
void hgemm_kernel(const __half* __restrict__ A, const __half* __restrict__ B,
                  const float* __restrict__ bias, void* __restrict__ Cout,
                  int M, int N, int K) {
    extern __shared__ char smraw[];
    u32 sm0 = s2u(smraw);

    int tid = threadIdx.x;
    int lane = tid & 31, warp = tid >> 5;
    int row0 = blockIdx.y * GBM;
    int col0 = blockIdx.x * GBN;
    int wr = (warp & 3) * 64;    // warp row offset (4 warps down)
    int wc = (warp >> 2) * 64;   // warp col offset (2 warps across)

    int nk = K / GBK;

    float acc[4][8][4];
    #pragma unroll
    for (int i = 0; i < 4; i++)
        #pragma unroll
        for (int j = 0; j < 8; j++)
            #pragma unroll
            for (int c = 0; c < 4; c++) acc[i][j][c] = 0.f;

    auto load_stage = [&](int st, int t) {
        u32 sa = sm0 + st * ST_BYTES;
        u32 sb = sa + A_ST_BYTES;
        const __half* Ab = A + (size_t)row0 * K + (size_t)t * GBK;
        const __half* Bb = B + (size_t)t * GBK * N + col0;
        #pragma unroll
        for (int q = 0; q < 4; q++) {
            int seg = tid + (q << 8);
            int r = seg >> 2, c8 = (seg & 3) * 8;
            cpa16(sa + (r * APITCH + c8) * 2, Ab + (size_t)r * K + c8);
        }
        #pragma unroll
        for (int q = 0; q < 2; q++) {
            int seg = tid + (q << 8);
            int r = seg >> 4, c8 = (seg & 15) * 8;
            cpa16(sb + (r * BPITCH + c8) * 2, Bb + (size_t)r * N + c8);
        }
        asm volatile("cp.async.commit_group;" ::);
    };

    load_stage(0, 0);
    load_stage(1, 1);

    for (int t = 0; t < nk; t++) {
        if (t + 1 < nk) { asm volatile("cp.async.wait_group 1;" ::); }
        else            { asm volatile("cp.async.wait_group 0;" ::); }
        __syncthreads();
        if (t + 2 < nk) load_stage((t + 2) % 3, t + 2);

        int st = t % 3;
        u32 sa = sm0 + st * ST_BYTES;
        u32 sb = sa + A_ST_BYTES;
        #pragma unroll
        for (int kk = 0; kk < GBK; kk += 16) {
            u32 a[4][4];
            #pragma unroll
            for (int i = 0; i < 4; i++) {
                int r = wr + i * 16 + (lane & 15);
                int c = kk + ((lane >> 4) << 3);
                ldm_x4(a[i], sa + (r * APITCH + c) * 2);
            }
            #pragma unroll
            for (int jj = 0; jj < 4; jj++) {
                u32 b[4];
                int r = kk + (lane & 15);
                int c = wc + jj * 16 + ((lane >> 4) << 3);
                ldm_x4_t(b, sb + (r * BPITCH + c) * 2);
                #pragma unroll
                for (int i = 0; i < 4; i++) {
                    mma16816(acc[i][jj*2],     a[i], b[0], b[1]);
                    mma16816(acc[i][jj*2 + 1], a[i], b[2], b[3]);
                }
            }
        }
        __syncthreads();
    }

    // epilogue
    int r1 = lane >> 2, c1 = (lane & 3) * 2;
    float* Cf = (float*)Cout;
    __half* Ch = (__half*)Cout;
    #pragma unroll
    for (int i = 0; i < 4; i++) {
        int gr0 = row0 + wr + i * 16 + r1;
        #pragma unroll
        for (int j = 0; j < 8; j++) {
            int gc = col0 + wc + j * 8 + c1;
            float b0 = bias[gc], b1 = bias[gc + 1];
            float v00 = acc[i][j][0] + b0, v01 = acc[i][j][1] + b1;
            float v10 = acc[i][j][2] + b0, v11 = acc[i][j][3] + b1;
            if (GELU) {
                v00 = 0.5f * v00 * (1.f + erff(v00 * 0.70710678f));
                v01 = 0.5f * v01 * (1.f + erff(v01 * 0.70710678f));
                v10 = 0.5f * v10 * (1.f + erff(v10 * 0.70710678f));
                v11 = 0.5f * v11 * (1.f + erff(v11 * 0.70710678f));
            }
            if (OUTH) {
                *(__half2*)(Ch + (size_t)gr0 * N + gc)       = __floats2half2_rn(v00, v01);
                *(__half2*)(Ch + (size_t)(gr0 + 8) * N + gc) = __floats2half2_rn(v10, v11);
            } else {
                *(float2*)(Cf + (size_t)gr0 * N + gc)       = make_float2(v00, v01);
                *(float2*)(Cf + (size_t)(gr0 + 8) * N + gc) = make_float2(v10, v11);
            }
        }
    }
}

// ---------------- fp16 tensor-core flash attention (Round-5, passing) ------
#define AP 72

__global__ __launch_bounds__(128)
void fattn_kernel(const __half* __restrict__ Q, const __half* __restrict__ K,
                  const __half* __restrict__ V, __half* __restrict__ O) {
    __shared__ __half Qs[64][AP];
    __shared__ __half Ks[2][64][AP];
    __shared__ __half Vs[2][64][AP];

    int tid = threadIdx.x, lane = tid & 31, warp = tid >> 5;
    int qt = blockIdx.x, h = blockIdx.y, b = blockIdx.z;
    int q0 = qt * 64;
    size_t base = (size_t)b * SS * DD + h * HD;

    for (int i = tid; i < 512; i += 128) {
        int r = i >> 3, c8 = (i & 7) * 8;
        cpa16(s2u(&Qs[r][c8]),    Q + base + (size_t)(q0 + r) * DD + c8);
        cpa16(s2u(&Ks[0][r][c8]), K + base + (size_t)r * DD + c8);
        cpa16(s2u(&Vs[0][r][c8]), V + base + (size_t)r * DD + c8);
    }
    asm volatile("cp.async.commit_group;" ::);
    asm volatile("cp.async.wait_group 0;" ::);
    __syncthreads();

    u32 qf[4][4];
    #pragma unroll
    for (int kc = 0; kc < 4; kc++)
        ldm_x4(qf[kc], s2u(&Qs[warp*16 + (lane & 15)][kc*16 + ((lane >> 4) << 3)]));

    float o[8][4];
    #pragma unroll
    for (int j = 0; j < 8; j++)
        #pragma unroll
        for (int c = 0; c < 4; c++) o[j][c] = 0.f;
    float m0 = -1e30f, m1 = -1e30f, l0 = 0.f, l1 = 0.f;

    int r0 = lane >> 2;
    int rowg0 = q0 + warp * 16 + r0;
    int rowg1 = rowg0 + 8;

    for (int kt = 0; kt <= qt; kt++) {
        int buf = kt & 1;
        if (kt > 0) {
            asm volatile("cp.async.wait_group 0;" ::);
            __syncthreads();
        }
        if (kt < qt) {
            int nb = buf ^ 1;
            size_t kb = base + (size_t)(kt + 1) * 64 * DD;
            for (int i = tid; i < 512; i += 128) {
                int r = i >> 3, c8 = (i & 7) * 8;
                cpa16(s2u(&Ks[nb][r][c8]), K + kb + (size_t)r * DD + c8);
                cpa16(s2u(&Vs[nb][r][c8]), V + kb + (size_t)r * DD + c8);
            }
            asm volatile("cp.async.commit_group;" ::);
        }

        float s[8][4];
        #pragma unroll
        for (int j = 0; j < 8; j++)
            #pragma unroll
            for (int c = 0; c < 4; c++) s[j][c] = 0.f;
        #pragma unroll
        for (int kc = 0; kc < 4; kc++) {
            #pragma unroll
            for (int kg = 0; kg < 4; kg++) {
                u32 kb4[4];
                ldm_x4(kb4, s2u(&Ks[buf][kg*16 + (lane & 15)][kc*16 + ((lane >> 4) << 3)]));
                mma16816(s[kg*2],     qf[kc], kb4[0], kb4[2]);
                mma16816(s[kg*2 + 1], qf[kc], kb4[1], kb4[3]);
            }
        }

        int colb = kt * 64 + (lane & 3) * 2;
        float ml0 = -1e30f, ml1 = -1e30f;
        #pragma unroll
        for (int j = 0; j < 8; j++) {
            int c0 = colb + j * 8, c1 = c0 + 1;
            s[j][0] = (c0 <= rowg0) ? s[j][0] * 0.125f : -1e30f;
            s[j][1] = (c1 <= rowg0) ? s[j][1] * 0.125f : -1e30f;
            s[j][2] = (c0 <= rowg1) ? s[j][2] * 0.125f : -1e30f;
            s[j][3] = (c1 <= rowg1) ? s[j][3] * 0.125f : -1e30f;
            ml0 = fmaxf(ml0, fmaxf(s[j][0], s[j][1]));
            ml1 = fmaxf(ml1, fmaxf(s[j][2], s[j][3]));
        }
        ml0 = fmaxf(ml0, __shfl_xor_sync(0xffffffffu, ml0, 1));
        ml0 = fmaxf(ml0, __shfl_xor_sync(0xffffffffu, ml0, 2));
        ml1 = fmaxf(ml1, __shfl_xor_sync(0xffffffffu, ml1, 1));
        ml1 = fmaxf(ml1, __shfl_xor_sync(0xffffffffu, ml1, 2));
        float mn0 = fmaxf(m0, ml0), mn1 = fmaxf(m1, ml1);
        float al0 = __expf(m0 - mn0), al1 = __expf(m1 - mn1);

        u32 pf[4][4];
        float la0 = 0.f, la1 = 0.f;
        #pragma unroll
        for (int j = 0; j < 8; j++) {
            float p0 = __expf(s[j][0] - mn0), p1 = __expf(s[j][1] - mn0);
            float p2 = __expf(s[j][2] - mn1), p3 = __expf(s[j][3] - mn1);
            la0 += p0 + p1;
            la1 += p2 + p3;
            int kc = j >> 1;
            if ((j & 1) == 0) {
                pf[kc][0] = packh2(p0, p1);
                pf[kc][1] = packh2(p2, p3);
            } else {
                pf[kc][2] = packh2(p0, p1);
                pf[kc][3] = packh2(p2, p3);
            }
        }
        la0 += __shfl_xor_sync(0xffffffffu, la0, 1);
        la0 += __shfl_xor_sync(0xffffffffu, la0, 2);
        la1 += __shfl_xor_sync(0xffffffffu, la1, 1);
        la1 += __shfl_xor_sync(0xffffffffu, la1, 2);
        l0 = l0 * al0 + la0;
        l1 = l1 * al1 + la1;
        m0 = mn0; m1 = mn1;

        #pragma unroll
        for (int j = 0; j < 8; j++) {
            o[j][0] *= al0; o[j][1] *= al0;
            o[j][2] *= al1; o[j][3] *= al1;
        }
        #pragma unroll
        for (int kc = 0; kc < 4; kc++) {
            #pragma unroll
            for (int nn = 0; nn < 4; nn++) {
                u32 vb[4];
                ldm_x4_t(vb, s2u(&Vs[buf][kc*16 + (lane & 15)][nn*16 + ((lane >> 4) << 3)]));
                mma16816(o[nn*2],     pf[kc], vb[0], vb[1]);
                mma16816(o[nn*2 + 1], pf[kc], vb[2], vb[3]);
            }
        }
    }

    float il0 = 1.f / l0, il1 = 1.f / l1;
    size_t ob = (size_t)(b * SS + q0 + warp * 16 + r0) * DD + h * HD;
    #pragma unroll
    for (int j = 0; j < 8; j++) {
        int col = j * 8 + (lane & 3) * 2;
        *(__half2*)(O + ob + col)        = __floats2half2_rn(o[j][0]*il0, o[j][1]*il0);
        *(__half2*)(O + ob + 8*DD + col) = __floats2half2_rn(o[j][2]*il1, o[j][3]*il1);
    }
}

// ---------------- fused residual + LayerNorm (dual output) ------------------
__inline__ __device__ float warp_sum(float v) {
    #pragma unroll
    for (int o = 16; o; o >>= 1) v += __shfl_xor_sync(0xffffffffu, v, o);
    return v;
}

__global__ __launch_bounds__(256)
void resid_ln_kernel(const float* __restrict__ a, const float* __restrict__ r,
                     const float* __restrict__ w, const float* __restrict__ bb,
                     float* __restrict__ out, __half* __restrict__ out16) {
    int row = blockIdx.x, tid = threadIdx.x;
    const float4* pa = (const float4*)(a + (size_t)row * DD);
    const float4* pr = (const float4*)(r + (size_t)row * DD);
    float4 av = pa[tid], rv = pr[tid];
    float x0 = av.x + rv.x, x1 = av.y + rv.y, x2 = av.z + rv.z, x3 = av.w + rv.w;
    float s  = x0 + x1 + x2 + x3;
    float s2 = x0*x0 + x1*x1 + x2*x2 + x3*x3;
    s = warp_sum(s);
    s2 = warp_sum(s2);
    __shared__ float sh[2][8];
    int wid = tid >> 5;
    if ((tid & 31) == 0) { sh[0][wid] = s; sh[1][wid] = s2; }
    __syncthreads();
    if (tid == 0) {
        float S = 0.f, S2 = 0.f;
        #pragma unroll
        for (int i = 0; i < 8; i++) { S += sh[0][i]; S2 += sh[1][i]; }
        sh[0][0] = S; sh[1][0] = S2;
    }
    __syncthreads();
    float mean = sh[0][0] * (1.f / DD);
    float var  = sh[1][0] * (1.f / DD) - mean * mean;
    float rstd = rsqrtf(var + 1e-5f);
    const float4* pw = (const float4*)w;
    const float4* pb = (const float4*)bb;
    float4 wv = pw[tid], bv = pb[tid];
    float4 ov;
    ov.x = (x0 - mean) * rstd * wv.x + bv.x;
    ov.y = (x1 - mean) * rstd * wv.y + bv.y;
    ov.z = (x2 - mean) * rstd * wv.z + bv.z;
    ov.w = (x3 - mean) * rstd * wv.w + bv.w;
    ((float4*)(out + (size_t)row * DD))[tid] = ov;
    __half2* o16 = (__half2*)(out16 + (size_t)row * DD);
    o16[2*tid]     = __floats2half2_rn(ov.x, ov.y);
    o16[2*tid + 1] = __floats2half2_rn(ov.z, ov.w);
}

__global__ void copy_kernel(const float* __restrict__ src, float* __restrict__ dst) {
    int i = blockIdx.x * 256 + threadIdx.x;
    ((float4*)dst)[i] = ((const float4*)src)[i];
}

// ---------------- host ------------------------------------------------------
extern "C" void kernel_launch(void* const* d_in, const int* in_sizes, int n_in,
                              void* d_out, int out_size) {
    const void*  x    = d_in[0];
    const float* tok  = (const float*)d_in[1];
    const float* pos  = (const float*)d_in[2];
    const float* Wq   = (const float*)d_in[3];
    const float* bq   = (const float*)d_in[4];
    const float* Wk   = (const float*)d_in[5];
    const float* bk   = (const float*)d_in[6];
    const float* Wv   = (const float*)d_in[7];
    const float* bv   = (const float*)d_in[8];
    const float* Wo   = (const float*)d_in[9];
    const float* bo   = (const float*)d_in[10];
    const float* ln1w = (const float*)d_in[11];
    const float* ln1b = (const float*)d_in[12];
    const float* ln2w = (const float*)d_in[13];
    const float* ln2b = (const float*)d_in[14];
    const float* W1   = (const float*)d_in[15];
    const float* b1   = (const float*)d_in[16];
    const float* W2   = (const float*)d_in[17];
    const float* b2   = (const float*)d_in[18];
    const float* Wout = (const float*)d_in[19];
    const float* bout = (const float*)d_in[20];
    float* out = (float*)d_out;

    float *h = 0, *tmp = 0;
    __half *h16 = 0, *q16 = 0, *k16 = 0, *v16 = 0, *attn16 = 0, *ff16 = 0;
    __half *wq16 = 0, *wk16 = 0, *wv16 = 0, *wo16 = 0, *w1h = 0, *w2h = 0, *wouth = 0;
    int* flag = 0;
    cudaGetSymbolAddress((void**)&h,      g_h);
    cudaGetSymbolAddress((void**)&tmp,    g_tmp);
    cudaGetSymbolAddress((void**)&h16,    g_h16);
    cudaGetSymbolAddress((void**)&q16,    g_q16);
    cudaGetSymbolAddress((void**)&k16,    g_k16);
    cudaGetSymbolAddress((void**)&v16,    g_v16);
    cudaGetSymbolAddress((void**)&attn16, g_attn16);
    cudaGetSymbolAddress((void**)&ff16,   g_ff16);
    cudaGetSymbolAddress((void**)&wq16,   g_wq16);
    cudaGetSymbolAddress((void**)&wk16,   g_wk16);
    cudaGetSymbolAddress((void**)&wv16,   g_wv16);
    cudaGetSymbolAddress((void**)&wo16,   g_wo16);
    cudaGetSymbolAddress((void**)&w1h,    g_w1h);
    cudaGetSymbolAddress((void**)&w2h,    g_w2h);
    cudaGetSymbolAddress((void**)&wouth,  g_wouth);
    cudaGetSymbolAddress((void**)&flag,   g_flag);

    cudaFuncSetAttribute(hgemm_kernel<false, false>,
                         cudaFuncAttributeMaxDynamicSharedMemorySize, G_SMEM);
    cudaFuncSetAttribute(hgemm_kernel<false, true>,
                         cudaFuncAttributeMaxDynamicSharedMemorySize, G_SMEM);
    cudaFuncSetAttribute(hgemm_kernel<true, true>,
                         cudaFuncAttributeMaxDynamicSharedMemorySize, G_SMEM);

    detect_kernel<<<1, 256>>>((const int*)x, flag);
    embed_kernel<<<TT, 256>>>(x, tok, pos, h, h16, flag);
    f2h_kernel<<<(DD * VV / 4 + 255) / 256, 256>>>(Wout, wouth, DD * VV / 4);

    dim3 gD(DD / GBN, TT / GBM);
    dim3 gF(FF / GBN, TT / GBM);
    dim3 gV(VV / GBN, TT / GBM);

    for (int l = 0; l < LL; l++) {
        size_t woff = (size_t)l * HH * DD * HD;
        repack_kernel<<<DD * DD / 256, 256>>>(Wq + woff, wq16);
        repack_kernel<<<DD * DD / 256, 256>>>(Wk + woff, wk16);
        repack_kernel<<<DD * DD / 256, 256>>>(Wv + woff, wv16);
        f2h_kernel<<<DD * DD / 1024, 256>>>(Wo + (size_t)l * DD * DD, wo16, DD * DD / 4);
        f2h_kernel<<<DD * FF / 1024, 256>>>(W1 + (size_t)l * DD * FF, w1h, DD * FF / 4);
        f2h_kernel<<<FF * DD / 1024, 256>>>(W2 + (size_t)l * FF * DD, w2h, FF * DD / 4);

        hgemm_kernel<false, true><<<gD, 256, G_SMEM>>>(h16, wq16, bq + l * DD, q16, TT, DD, DD);
        hgemm_kernel<false, true><<<gD, 256, G_SMEM>>>(h16, wk16, bk + l * DD, k16, TT, DD, DD);
        hgemm_kernel<false, true><<<gD, 256, G_SMEM>>>(h16, wv16, bv + l * DD, v16, TT, DD, DD);

        dim3 ga(SS / 64, HH, BB);
        fattn_kernel<<<ga, 128>>>(q16, k16, v16, attn16);

        hgemm_kernel<false, false><<<gD, 256, G_SMEM>>>(attn16, wo16, bo + l * DD, tmp, TT, DD, DD);
        resid_ln_kernel<<<TT, 256>>>(h, tmp, ln1w + l * DD, ln1b + l * DD, h, h16);

        hgemm_kernel<true, true><<<gF, 256, G_SMEM>>>(h16, w1h, b1 + l * FF, ff16, TT, FF, DD);
        hgemm_kernel<false, false><<<gD, 256, G_SMEM>>>(ff16, w2h, b2 + l * DD, tmp, TT, DD, FF);
        resid_ln_kernel<<<TT, 256>>>(h, tmp, ln2w + l * DD, ln2b + l * DD, h, h16);
    }

    hgemm_kernel<false, false><<<gV, 256, G_SMEM>>>(h16, wouth, bout, out, TT, VV, DD);
    copy_kernel<<<TT * DD / 4 / 256, 256>>>(h, out + (size_t)TT * VV);
}